// round 4
// baseline (speedup 1.0000x reference)
#include <cuda_runtime.h>

#define BATCH 8
#define TLEN 2048
#define DIN 1024
#define HD 64
#define BT (BATCH*TLEN)

// Scratch for projections (no cudaMalloc allowed)
__device__ float g_q[BT*HD];
__device__ float g_k[BT*HD];
__device__ float g_v[BT*HD];

// ---------------------------------------------------------------------------
// Projection GEMM: out[BT,64] = x[BT,1024] @ W[1024,64]
// blockIdx.y selects Wq/Wk/Wv; 64x64 output tile, 256 threads, 4x4 microtile.
// ---------------------------------------------------------------------------
__global__ __launch_bounds__(256) void proj_kernel(
    const float* __restrict__ x,
    const float* __restrict__ Wq,
    const float* __restrict__ Wk,
    const float* __restrict__ Wv)
{
    const float* W = (blockIdx.y == 0) ? Wq : ((blockIdx.y == 1) ? Wk : Wv);
    float* out = (blockIdx.y == 0) ? g_q : ((blockIdx.y == 1) ? g_k : g_v);

    __shared__ float xs[16][64];   // [k][row]
    __shared__ float ws[16][64];   // [k][col]

    const int tid = threadIdx.x;
    const int row0 = blockIdx.x * 64;
    const int ty = tid >> 4;       // 0..15 -> row group
    const int tx = tid & 15;       // 0..15 -> col group

    float acc[4][4];
#pragma unroll
    for (int i = 0; i < 4; i++)
#pragma unroll
        for (int j = 0; j < 4; j++) acc[i][j] = 0.f;

    for (int k0 = 0; k0 < DIN; k0 += 16) {
        {   // load x tile 64 rows x 16 k (transposed into xs[k][row])
            int r = tid >> 2;
            int kc = (tid & 3) * 4;
            float4 xv = *(const float4*)&x[(size_t)(row0 + r) * DIN + k0 + kc];
            xs[kc + 0][r] = xv.x;
            xs[kc + 1][r] = xv.y;
            xs[kc + 2][r] = xv.z;
            xs[kc + 3][r] = xv.w;
        }
        {   // load W tile 16 k x 64 cols
            int wr = tid >> 4;
            int wc = (tid & 15) * 4;
            *(float4*)&ws[wr][wc] = *(const float4*)&W[(size_t)(k0 + wr) * HD + wc];
        }
        __syncthreads();

#pragma unroll
        for (int kk = 0; kk < 16; kk++) {
            float a[4], b[4];
            *(float4*)a = *(const float4*)&xs[kk][ty * 4];
            *(float4*)b = *(const float4*)&ws[kk][tx * 4];
#pragma unroll
            for (int i = 0; i < 4; i++)
#pragma unroll
                for (int j = 0; j < 4; j++) acc[i][j] += a[i] * b[j];
        }
        __syncthreads();
    }

#pragma unroll
    for (int i = 0; i < 4; i++) {
        float4 o = make_float4(acc[i][0], acc[i][1], acc[i][2], acc[i][3]);
        *(float4*)&out[(size_t)(row0 + ty * 4 + i) * HD + tx * 4] = o;
    }
}

// ---------------------------------------------------------------------------
// Flash attention with swapped roles: scores[t][s] = (K[t] . Q[s]) * 64^-0.5,
// causal (s <= t), softmax over s, out[t] = sum_s p * V[s].
// 256 threads = 64 rows x 4 threads/row (16 head dims each).
// Tiles of 64 s-positions staged in shared. Reversed tile order for balance.
// ---------------------------------------------------------------------------
__global__ __launch_bounds__(256) void attn_kernel(float* __restrict__ out)
{
    __shared__ float qs[64][64];
    __shared__ float vs[64][64];

    const int b = blockIdx.y;
    const int tile = (gridDim.x - 1) - blockIdx.x;   // big tiles first
    const int tid = threadIdx.x;
    const int row = tid >> 2;          // 0..63, row within tile
    const int h0 = (tid & 3) * 16;     // head-dim slice

    const int t = tile * 64 + row;

    // K row slice (16 floats) in registers
    float kreg[16];
    {
        const float* Kp = g_k + ((size_t)b * TLEN + t) * HD + h0;
#pragma unroll
        for (int i = 0; i < 4; i++)
            *(float4*)&kreg[i * 4] = *(const float4*)&Kp[i * 4];
    }

    float m = -1e30f;
    float l = 0.f;
    float acc[16];
#pragma unroll
    for (int i = 0; i < 16; i++) acc[i] = 0.f;

    const int send = tile * 64;
    for (int s0 = 0; s0 <= send; s0 += 64) {
        // stage Q and V tiles: 64x64 each, 8 float4 per thread total
#pragma unroll
        for (int i = 0; i < 4; i++) {
            int idx = tid + i * 256;
            int sr = idx >> 4;
            int c4 = (idx & 15) * 4;
            size_t g = ((size_t)b * TLEN + s0 + sr) * HD + c4;
            *(float4*)&qs[sr][c4] = *(const float4*)&g_q[g];
            *(float4*)&vs[sr][c4] = *(const float4*)&g_v[g];
        }
        __syncthreads();

        const bool diag = (s0 == send);
        // uniform per-warp bound (all 32 lanes of a warp share row>>3)
        const int jmaxw = diag ? (row | 7) : 63;

        for (int jj = 0; jj <= jmaxw; jj += 16) {
            float p[16];
            float cmax = -1e30f;
#pragma unroll
            for (int j2 = 0; j2 < 16; j2++) {
                const int j = jj + j2;
                float4 q0 = *(const float4*)&qs[j][h0];
                float4 q1 = *(const float4*)&qs[j][h0 + 4];
                float4 q2 = *(const float4*)&qs[j][h0 + 8];
                float4 q3 = *(const float4*)&qs[j][h0 + 12];
                float sc = kreg[0] * q0.x + kreg[1] * q0.y + kreg[2] * q0.z + kreg[3] * q0.w
                         + kreg[4] * q1.x + kreg[5] * q1.y + kreg[6] * q1.z + kreg[7] * q1.w
                         + kreg[8] * q2.x + kreg[9] * q2.y + kreg[10] * q2.z + kreg[11] * q2.w
                         + kreg[12] * q3.x + kreg[13] * q3.y + kreg[14] * q3.z + kreg[15] * q3.w;
                // reduce across the 4 threads of this row (lanes grouped by 4)
                sc += __shfl_xor_sync(0xffffffffu, sc, 1);
                sc += __shfl_xor_sync(0xffffffffu, sc, 2);
                sc *= 0.125f;   // 64^-0.5
                if (diag && j > row) sc = -1e30f;
                p[j2] = sc;
                cmax = fmaxf(cmax, sc);
            }

            const float mnew = fmaxf(m, cmax);
            const float corr = __expf(m - mnew);
            l *= corr;
#pragma unroll
            for (int i = 0; i < 16; i++) acc[i] *= corr;

#pragma unroll
            for (int j2 = 0; j2 < 16; j2++) {
                const int j = jj + j2;
                const float e = __expf(p[j2] - mnew);
                l += e;
                float4 v0 = *(const float4*)&vs[j][h0];
                float4 v1 = *(const float4*)&vs[j][h0 + 4];
                float4 v2 = *(const float4*)&vs[j][h0 + 8];
                float4 v3 = *(const float4*)&vs[j][h0 + 12];
                acc[0]  += e * v0.x; acc[1]  += e * v0.y; acc[2]  += e * v0.z; acc[3]  += e * v0.w;
                acc[4]  += e * v1.x; acc[5]  += e * v1.y; acc[6]  += e * v1.z; acc[7]  += e * v1.w;
                acc[8]  += e * v2.x; acc[9]  += e * v2.y; acc[10] += e * v2.z; acc[11] += e * v2.w;
                acc[12] += e * v3.x; acc[13] += e * v3.y; acc[14] += e * v3.z; acc[15] += e * v3.w;
            }
            m = mnew;
        }
        __syncthreads();
    }

    const float inv = 1.f / l;
    float* op = out + ((size_t)b * TLEN + t) * HD + h0;
#pragma unroll
    for (int i = 0; i < 4; i++) {
        float4 o = make_float4(acc[i * 4 + 0] * inv, acc[i * 4 + 1] * inv,
                               acc[i * 4 + 2] * inv, acc[i * 4 + 3] * inv);
        *(float4*)&op[i * 4] = o;
    }
}

extern "C" void kernel_launch(void* const* d_in, const int* in_sizes, int n_in,
                              void* d_out, int out_size)
{
    const float* x  = (const float*)d_in[0];
    const float* Wq = (const float*)d_in[1];
    const float* Wk = (const float*)d_in[2];
    const float* Wv = (const float*)d_in[3];
    float* out = (float*)d_out;

    proj_kernel<<<dim3(BT / 64, 3), 256>>>(x, Wq, Wk, Wv);
    attn_kernel<<<dim3(TLEN / 64, BATCH), 256>>>(out);
}

// round 5
// speedup vs baseline: 4.9387x; 4.9387x over previous
#include <cuda_runtime.h>
#include <cstdint>
#include <cstddef>

#define BATCH 8
#define TLEN 2048
#define DIN 1024
#define HD 64
#define BT (BATCH*TLEN)

// Scratch for projections (no cudaMalloc allowed)
__device__ float g_q[BT*HD];
__device__ float g_k[BT*HD];
__device__ float g_v[BT*HD];

// ---------------------------------------------------------------------------
// tf32 helpers
// ---------------------------------------------------------------------------
__device__ __forceinline__ uint32_t f2tf32(float f) {
    uint32_t u;
    asm("cvt.rna.tf32.f32 %0, %1;" : "=r"(u) : "f"(f));
    return u;
}

__device__ __forceinline__ void mma_tf32(
    float& c0, float& c1, float& c2, float& c3,
    uint32_t a0, uint32_t a1, uint32_t a2, uint32_t a3,
    uint32_t b0, uint32_t b1)
{
    asm volatile(
        "mma.sync.aligned.m16n8k8.row.col.f32.tf32.tf32.f32 "
        "{%0,%1,%2,%3}, {%4,%5,%6,%7}, {%8,%9}, {%0,%1,%2,%3};"
        : "+f"(c0), "+f"(c1), "+f"(c2), "+f"(c3)
        : "r"(a0), "r"(a1), "r"(a2), "r"(a3), "r"(b0), "r"(b1));
}

// ---------------------------------------------------------------------------
// Fused projection GEMM (tf32 tensor cores):
// [16384,1024] x [1024, 64x3] -> g_q, g_k, g_v
// Block: 128 rows x 192 cols, 256 threads = 8 warps (2x4), warp tile 64x48.
// ---------------------------------------------------------------------------
#define XS_PAD 20
#define WS_PAD 200

__global__ __launch_bounds__(256) void proj_mma_kernel(
    const float* __restrict__ x,
    const float* __restrict__ Wq,
    const float* __restrict__ Wk,
    const float* __restrict__ Wv)
{
    __shared__ float xs[128 * XS_PAD];   // [row][k], tf32-rounded
    __shared__ float ws[16 * WS_PAD];    // [k][col 0..191], tf32-rounded

    const int tid  = threadIdx.x;
    const int lane = tid & 31;
    const int warp = tid >> 5;
    const int wm = warp >> 2;   // 0..1 : 64-row half
    const int wn = warp & 3;    // 0..3 : 48-col slice
    const int row0 = blockIdx.x * 128;

    float c[4][6][4];
#pragma unroll
    for (int mt = 0; mt < 4; mt++)
#pragma unroll
        for (int nt = 0; nt < 6; nt++)
#pragma unroll
            for (int f = 0; f < 4; f++) c[mt][nt][f] = 0.f;

    // staging indices
    const int xr = tid >> 2;            // with +64 for second chunk
    const int xk4 = (tid & 3) * 4;
    const int wkr = tid >> 4;
    const int wnc = (tid & 15) * 4;

    float4 px0, px1, pw0, pw1, pw2;

    // prefetch tile 0
    {
        px0 = *(const float4*)&x[(size_t)(row0 + xr) * DIN + 0 + xk4];
        px1 = *(const float4*)&x[(size_t)(row0 + xr + 64) * DIN + 0 + xk4];
        pw0 = *(const float4*)&Wq[(size_t)(0 + wkr) * HD + wnc];
        pw1 = *(const float4*)&Wk[(size_t)(0 + wkr) * HD + wnc];
        pw2 = *(const float4*)&Wv[(size_t)(0 + wkr) * HD + wnc];
    }
    // store tile 0
    {
        float* p = &xs[xr * XS_PAD + xk4];
        p[0] = __uint_as_float(f2tf32(px0.x)); p[1] = __uint_as_float(f2tf32(px0.y));
        p[2] = __uint_as_float(f2tf32(px0.z)); p[3] = __uint_as_float(f2tf32(px0.w));
        p = &xs[(xr + 64) * XS_PAD + xk4];
        p[0] = __uint_as_float(f2tf32(px1.x)); p[1] = __uint_as_float(f2tf32(px1.y));
        p[2] = __uint_as_float(f2tf32(px1.z)); p[3] = __uint_as_float(f2tf32(px1.w));
        p = &ws[wkr * WS_PAD + 0 + wnc];
        p[0] = __uint_as_float(f2tf32(pw0.x)); p[1] = __uint_as_float(f2tf32(pw0.y));
        p[2] = __uint_as_float(f2tf32(pw0.z)); p[3] = __uint_as_float(f2tf32(pw0.w));
        p = &ws[wkr * WS_PAD + 64 + wnc];
        p[0] = __uint_as_float(f2tf32(pw1.x)); p[1] = __uint_as_float(f2tf32(pw1.y));
        p[2] = __uint_as_float(f2tf32(pw1.z)); p[3] = __uint_as_float(f2tf32(pw1.w));
        p = &ws[wkr * WS_PAD + 128 + wnc];
        p[0] = __uint_as_float(f2tf32(pw2.x)); p[1] = __uint_as_float(f2tf32(pw2.y));
        p[2] = __uint_as_float(f2tf32(pw2.z)); p[3] = __uint_as_float(f2tf32(pw2.w));
    }
    __syncthreads();

    for (int kt = 0; kt < 64; kt++) {
        if (kt < 63) {
            const int k0n = (kt + 1) * 16;
            px0 = *(const float4*)&x[(size_t)(row0 + xr) * DIN + k0n + xk4];
            px1 = *(const float4*)&x[(size_t)(row0 + xr + 64) * DIN + k0n + xk4];
            pw0 = *(const float4*)&Wq[(size_t)(k0n + wkr) * HD + wnc];
            pw1 = *(const float4*)&Wk[(size_t)(k0n + wkr) * HD + wnc];
            pw2 = *(const float4*)&Wv[(size_t)(k0n + wkr) * HD + wnc];
        }

#pragma unroll
        for (int ks = 0; ks < 2; ks++) {
            const int kc = ks * 8 + (lane & 3);
            uint32_t a[4][4];
#pragma unroll
            for (int mt = 0; mt < 4; mt++) {
                const int rb = wm * 64 + mt * 16 + (lane >> 2);
                a[mt][0] = __float_as_uint(xs[rb * XS_PAD + kc]);
                a[mt][1] = __float_as_uint(xs[(rb + 8) * XS_PAD + kc]);
                a[mt][2] = __float_as_uint(xs[rb * XS_PAD + kc + 4]);
                a[mt][3] = __float_as_uint(xs[(rb + 8) * XS_PAD + kc + 4]);
            }
#pragma unroll
            for (int nt = 0; nt < 6; nt++) {
                const int nb = wn * 48 + nt * 8 + (lane >> 2);
                uint32_t b0 = __float_as_uint(ws[kc * WS_PAD + nb]);
                uint32_t b1 = __float_as_uint(ws[(kc + 4) * WS_PAD + nb]);
#pragma unroll
                for (int mt = 0; mt < 4; mt++)
                    mma_tf32(c[mt][nt][0], c[mt][nt][1], c[mt][nt][2], c[mt][nt][3],
                             a[mt][0], a[mt][1], a[mt][2], a[mt][3], b0, b1);
            }
        }
        __syncthreads();
        if (kt < 63) {
            float* p = &xs[xr * XS_PAD + xk4];
            p[0] = __uint_as_float(f2tf32(px0.x)); p[1] = __uint_as_float(f2tf32(px0.y));
            p[2] = __uint_as_float(f2tf32(px0.z)); p[3] = __uint_as_float(f2tf32(px0.w));
            p = &xs[(xr + 64) * XS_PAD + xk4];
            p[0] = __uint_as_float(f2tf32(px1.x)); p[1] = __uint_as_float(f2tf32(px1.y));
            p[2] = __uint_as_float(f2tf32(px1.z)); p[3] = __uint_as_float(f2tf32(px1.w));
            p = &ws[wkr * WS_PAD + 0 + wnc];
            p[0] = __uint_as_float(f2tf32(pw0.x)); p[1] = __uint_as_float(f2tf32(pw0.y));
            p[2] = __uint_as_float(f2tf32(pw0.z)); p[3] = __uint_as_float(f2tf32(pw0.w));
            p = &ws[wkr * WS_PAD + 64 + wnc];
            p[0] = __uint_as_float(f2tf32(pw1.x)); p[1] = __uint_as_float(f2tf32(pw1.y));
            p[2] = __uint_as_float(f2tf32(pw1.z)); p[3] = __uint_as_float(f2tf32(pw1.w));
            p = &ws[wkr * WS_PAD + 128 + wnc];
            p[0] = __uint_as_float(f2tf32(pw2.x)); p[1] = __uint_as_float(f2tf32(pw2.y));
            p[2] = __uint_as_float(f2tf32(pw2.z)); p[3] = __uint_as_float(f2tf32(pw2.w));
            __syncthreads();
        }
    }

    // epilogue: scatter fragments to g_q/g_k/g_v
#pragma unroll
    for (int mt = 0; mt < 4; mt++) {
        const int row = row0 + wm * 64 + mt * 16 + (lane >> 2);
#pragma unroll
        for (int nt = 0; nt < 6; nt++) {
            const int gcol = wn * 48 + nt * 8 + (lane & 3) * 2;
            float* op = (gcol < 64) ? g_q : ((gcol < 128) ? g_k : g_v);
            const int lcol = gcol & 63;
            *(float2*)&op[(size_t)row * HD + lcol] = make_float2(c[mt][nt][0], c[mt][nt][1]);
            *(float2*)&op[(size_t)(row + 8) * HD + lcol] = make_float2(c[mt][nt][2], c[mt][nt][3]);
        }
    }
}

// ---------------------------------------------------------------------------
// Flash attention (swapped roles): S[t][s] = (K[t].Q[s])/8, causal s<=t,
// softmax over s, O[t] = sum_s P * V[s].
// Block: 64 t-rows, 256 threads. Two smem GEMMs with 4x4 register microtiles.
// Causal balance: block x processes tiles x and 31-x (constant 33 tile-steps).
// ---------------------------------------------------------------------------
#define SPAD 68
#define ATTN_SMEM_FLOATS (4*64*SPAD + 192)
#define ATTN_SMEM_BYTES  (ATTN_SMEM_FLOATS * 4)

__global__ __launch_bounds__(256) void attn_kernel(float* __restrict__ out)
{
    extern __shared__ float sm[];
    float* kst = sm;                 // [h][r] transposed K tile
    float* qst = kst + 64 * SPAD;    // [h][c] transposed Q tile
    float* vsm = qst + 64 * SPAD;    // [c][d] V tile
    float* ps  = vsm + 64 * SPAD;    // [r][c] scores / probs
    float* smL = ps + 64 * SPAD;     // row sum l
    float* smM = smL + 64;           // row max m
    float* smC = smM + 64;           // row corr factor

    const int b = blockIdx.y;
    const int tid = threadIdx.x;
    const int ty = tid >> 4, tx = tid & 15;
    const int r0 = ty * 4, c0 = tx * 4;
    const size_t bbase = (size_t)b * TLEN;

    for (int ph = 0; ph < 2; ph++) {
        const int tile = ph ? (31 - (int)blockIdx.x) : (int)blockIdx.x;
        const int t0 = tile * 64;

        __syncthreads();   // guard smem reuse across phases
        // stage K^T for this tile
        const float* gk = g_k + (bbase + t0) * HD;
#pragma unroll
        for (int i = 0; i < 4; i++) {
            const int idx = tid + i * 256;
            const int r = idx >> 4, h4 = (idx & 15) * 4;
            float4 kv = *(const float4*)&gk[r * HD + h4];
            kst[(h4 + 0) * SPAD + r] = kv.x;
            kst[(h4 + 1) * SPAD + r] = kv.y;
            kst[(h4 + 2) * SPAD + r] = kv.z;
            kst[(h4 + 3) * SPAD + r] = kv.w;
        }
        if (tid < 64) { smL[tid] = 0.f; smM[tid] = -1e30f; }

        float o[4][4];
#pragma unroll
        for (int i = 0; i < 4; i++)
#pragma unroll
            for (int j = 0; j < 4; j++) o[i][j] = 0.f;

        for (int s0 = 0; s0 <= t0; s0 += 64) {
            __syncthreads();
            // stage Q^T and V
            const float* gq = g_q + (bbase + s0) * HD;
            const float* gv = g_v + (bbase + s0) * HD;
#pragma unroll
            for (int i = 0; i < 4; i++) {
                const int idx = tid + i * 256;
                const int r = idx >> 4, h4 = (idx & 15) * 4;
                float4 qv = *(const float4*)&gq[r * HD + h4];
                qst[(h4 + 0) * SPAD + r] = qv.x;
                qst[(h4 + 1) * SPAD + r] = qv.y;
                qst[(h4 + 2) * SPAD + r] = qv.z;
                qst[(h4 + 3) * SPAD + r] = qv.w;
                *(float4*)&vsm[r * SPAD + h4] = *(const float4*)&gv[r * HD + h4];
            }
            __syncthreads();

            // GEMM1: S = K . Q^T  (accumulate over h)
            float s[4][4];
#pragma unroll
            for (int i = 0; i < 4; i++)
#pragma unroll
                for (int j = 0; j < 4; j++) s[i][j] = 0.f;

#pragma unroll 8
            for (int h = 0; h < 64; h++) {
                float4 a  = *(const float4*)&kst[h * SPAD + r0];
                float4 bq = *(const float4*)&qst[h * SPAD + c0];
                s[0][0] += a.x * bq.x; s[0][1] += a.x * bq.y; s[0][2] += a.x * bq.z; s[0][3] += a.x * bq.w;
                s[1][0] += a.y * bq.x; s[1][1] += a.y * bq.y; s[1][2] += a.y * bq.z; s[1][3] += a.y * bq.w;
                s[2][0] += a.z * bq.x; s[2][1] += a.z * bq.y; s[2][2] += a.z * bq.z; s[2][3] += a.z * bq.w;
                s[3][0] += a.w * bq.x; s[3][1] += a.w * bq.y; s[3][2] += a.w * bq.z; s[3][3] += a.w * bq.w;
            }

            const bool diag = (s0 == t0);
#pragma unroll
            for (int i = 0; i < 4; i++) {
                float4 w4;
                w4.x = s[i][0] * 0.125f; w4.y = s[i][1] * 0.125f;
                w4.z = s[i][2] * 0.125f; w4.w = s[i][3] * 0.125f;
                if (diag) {
                    const int r = r0 + i;
                    if (c0 + 0 > r) w4.x = -1e30f;
                    if (c0 + 1 > r) w4.y = -1e30f;
                    if (c0 + 2 > r) w4.z = -1e30f;
                    if (c0 + 3 > r) w4.w = -1e30f;
                }
                *(float4*)&ps[(r0 + i) * SPAD + c0] = w4;
            }
            __syncthreads();

            // softmax pass: 4 threads per row, 16 cols each
            {
                const int r = tid >> 2;
                const int cc = (tid & 3) * 16;
                float v[16];
                float mx = -1e30f;
#pragma unroll
                for (int j = 0; j < 4; j++) {
                    float4 p4 = *(const float4*)&ps[r * SPAD + cc + j * 4];
                    v[j * 4 + 0] = p4.x; v[j * 4 + 1] = p4.y;
                    v[j * 4 + 2] = p4.z; v[j * 4 + 3] = p4.w;
                    mx = fmaxf(mx, fmaxf(fmaxf(p4.x, p4.y), fmaxf(p4.z, p4.w)));
                }
                mx = fmaxf(mx, __shfl_xor_sync(0xffffffffu, mx, 1));
                mx = fmaxf(mx, __shfl_xor_sync(0xffffffffu, mx, 2));
                const float mold = smM[r];
                const float mnew = fmaxf(mold, mx);
                float lsum = 0.f;
#pragma unroll
                for (int j = 0; j < 16; j++) {
                    const float e = __expf(v[j] - mnew);
                    v[j] = e; lsum += e;
                }
#pragma unroll
                for (int j = 0; j < 4; j++)
                    *(float4*)&ps[r * SPAD + cc + j * 4] =
                        make_float4(v[j * 4 + 0], v[j * 4 + 1], v[j * 4 + 2], v[j * 4 + 3]);
                lsum += __shfl_xor_sync(0xffffffffu, lsum, 1);
                lsum += __shfl_xor_sync(0xffffffffu, lsum, 2);
                if ((tid & 3) == 0) {
                    const float corr = __expf(mold - mnew);
                    smC[r] = corr;
                    smM[r] = mnew;
                    smL[r] = smL[r] * corr + lsum;
                }
            }
            __syncthreads();

            // GEMM2: O = O*corr + P . V
#pragma unroll
            for (int i = 0; i < 4; i++) {
                const float corr = smC[r0 + i];
                o[i][0] *= corr; o[i][1] *= corr; o[i][2] *= corr; o[i][3] *= corr;
            }
#pragma unroll 8
            for (int cidx = 0; cidx < 64; cidx++) {
                float4 vv = *(const float4*)&vsm[cidx * SPAD + c0];
                const float a0 = ps[(r0 + 0) * SPAD + cidx];
                const float a1 = ps[(r0 + 1) * SPAD + cidx];
                const float a2 = ps[(r0 + 2) * SPAD + cidx];
                const float a3 = ps[(r0 + 3) * SPAD + cidx];
                o[0][0] += a0 * vv.x; o[0][1] += a0 * vv.y; o[0][2] += a0 * vv.z; o[0][3] += a0 * vv.w;
                o[1][0] += a1 * vv.x; o[1][1] += a1 * vv.y; o[1][2] += a1 * vv.z; o[1][3] += a1 * vv.w;
                o[2][0] += a2 * vv.x; o[2][1] += a2 * vv.y; o[2][2] += a2 * vv.z; o[2][3] += a2 * vv.w;
                o[3][0] += a3 * vv.x; o[3][1] += a3 * vv.y; o[3][2] += a3 * vv.z; o[3][3] += a3 * vv.w;
            }
        }

        // epilogue: normalize and store (smL final; last write precedes the
        // __syncthreads before GEMM2 of the final s-tile)
        float* op = out + (bbase + t0) * HD;
#pragma unroll
        for (int i = 0; i < 4; i++) {
            const float inv = 1.f / smL[r0 + i];
            float4 w4 = make_float4(o[i][0] * inv, o[i][1] * inv, o[i][2] * inv, o[i][3] * inv);
            *(float4*)&op[(r0 + i) * HD + c0] = w4;
        }
    }
}

extern "C" void kernel_launch(void* const* d_in, const int* in_sizes, int n_in,
                              void* d_out, int out_size)
{
    const float* x  = (const float*)d_in[0];
    const float* Wq = (const float*)d_in[1];
    const float* Wk = (const float*)d_in[2];
    const float* Wv = (const float*)d_in[3];
    float* out = (float*)d_out;

    cudaFuncSetAttribute(attn_kernel, cudaFuncAttributeMaxDynamicSharedMemorySize,
                         ATTN_SMEM_BYTES);

    proj_mma_kernel<<<BT / 128, 256>>>(x, Wq, Wk, Wv);
    attn_kernel<<<dim3(16, BATCH), 256, ATTN_SMEM_BYTES>>>(out);
}

// round 6
// speedup vs baseline: 8.5407x; 1.7293x over previous
#include <cuda_runtime.h>
#include <cstdint>
#include <cstddef>

#define BATCH 8
#define TLEN 2048
#define DIN 1024
#define HD 64
#define BT (BATCH*TLEN)

// Scratch for projections (no cudaMalloc allowed)
__device__ float g_q[BT*HD];
__device__ float g_k[BT*HD];
__device__ float g_v[BT*HD];

// ---------------------------------------------------------------------------
// tf32 helpers
// ---------------------------------------------------------------------------
__device__ __forceinline__ uint32_t f2tf32(float f) {
    uint32_t u;
    asm("cvt.rna.tf32.f32 %0, %1;" : "=r"(u) : "f"(f));
    return u;
}
__device__ __forceinline__ float f2tf32f(float f) {
    return __uint_as_float(f2tf32(f));
}

__device__ __forceinline__ void mma_tf32(
    float& c0, float& c1, float& c2, float& c3,
    uint32_t a0, uint32_t a1, uint32_t a2, uint32_t a3,
    uint32_t b0, uint32_t b1)
{
    asm volatile(
        "mma.sync.aligned.m16n8k8.row.col.f32.tf32.tf32.f32 "
        "{%0,%1,%2,%3}, {%4,%5,%6,%7}, {%8,%9}, {%0,%1,%2,%3};"
        : "+f"(c0), "+f"(c1), "+f"(c2), "+f"(c3)
        : "r"(a0), "r"(a1), "r"(a2), "r"(a3), "r"(b0), "r"(b1));
}

// ---------------------------------------------------------------------------
// Fused projection GEMM (tf32 tensor cores):
// [16384,1024] x [1024, 64x3] -> g_q, g_k, g_v
// Block: 128 rows x 192 cols, 256 threads = 8 warps (2x4), warp tile 64x48.
// ---------------------------------------------------------------------------
#define XS_PAD 20
#define WS_PAD 200

__global__ __launch_bounds__(256) void proj_mma_kernel(
    const float* __restrict__ x,
    const float* __restrict__ Wq,
    const float* __restrict__ Wk,
    const float* __restrict__ Wv)
{
    __shared__ float xs[128 * XS_PAD];
    __shared__ float ws[16 * WS_PAD];

    const int tid  = threadIdx.x;
    const int lane = tid & 31;
    const int warp = tid >> 5;
    const int wm = warp >> 2;
    const int wn = warp & 3;
    const int row0 = blockIdx.x * 128;

    float c[4][6][4];
#pragma unroll
    for (int mt = 0; mt < 4; mt++)
#pragma unroll
        for (int nt = 0; nt < 6; nt++)
#pragma unroll
            for (int f = 0; f < 4; f++) c[mt][nt][f] = 0.f;

    const int xr = tid >> 2;
    const int xk4 = (tid & 3) * 4;
    const int wkr = tid >> 4;
    const int wnc = (tid & 15) * 4;

    float4 px0, px1, pw0, pw1, pw2;

    {
        px0 = *(const float4*)&x[(size_t)(row0 + xr) * DIN + 0 + xk4];
        px1 = *(const float4*)&x[(size_t)(row0 + xr + 64) * DIN + 0 + xk4];
        pw0 = *(const float4*)&Wq[(size_t)(0 + wkr) * HD + wnc];
        pw1 = *(const float4*)&Wk[(size_t)(0 + wkr) * HD + wnc];
        pw2 = *(const float4*)&Wv[(size_t)(0 + wkr) * HD + wnc];
    }
    {
        float* p = &xs[xr * XS_PAD + xk4];
        p[0] = f2tf32f(px0.x); p[1] = f2tf32f(px0.y); p[2] = f2tf32f(px0.z); p[3] = f2tf32f(px0.w);
        p = &xs[(xr + 64) * XS_PAD + xk4];
        p[0] = f2tf32f(px1.x); p[1] = f2tf32f(px1.y); p[2] = f2tf32f(px1.z); p[3] = f2tf32f(px1.w);
        p = &ws[wkr * WS_PAD + 0 + wnc];
        p[0] = f2tf32f(pw0.x); p[1] = f2tf32f(pw0.y); p[2] = f2tf32f(pw0.z); p[3] = f2tf32f(pw0.w);
        p = &ws[wkr * WS_PAD + 64 + wnc];
        p[0] = f2tf32f(pw1.x); p[1] = f2tf32f(pw1.y); p[2] = f2tf32f(pw1.z); p[3] = f2tf32f(pw1.w);
        p = &ws[wkr * WS_PAD + 128 + wnc];
        p[0] = f2tf32f(pw2.x); p[1] = f2tf32f(pw2.y); p[2] = f2tf32f(pw2.z); p[3] = f2tf32f(pw2.w);
    }
    __syncthreads();

    for (int kt = 0; kt < 64; kt++) {
        if (kt < 63) {
            const int k0n = (kt + 1) * 16;
            px0 = *(const float4*)&x[(size_t)(row0 + xr) * DIN + k0n + xk4];
            px1 = *(const float4*)&x[(size_t)(row0 + xr + 64) * DIN + k0n + xk4];
            pw0 = *(const float4*)&Wq[(size_t)(k0n + wkr) * HD + wnc];
            pw1 = *(const float4*)&Wk[(size_t)(k0n + wkr) * HD + wnc];
            pw2 = *(const float4*)&Wv[(size_t)(k0n + wkr) * HD + wnc];
        }

#pragma unroll
        for (int ks = 0; ks < 2; ks++) {
            const int kc = ks * 8 + (lane & 3);
            uint32_t a[4][4];
#pragma unroll
            for (int mt = 0; mt < 4; mt++) {
                const int rb = wm * 64 + mt * 16 + (lane >> 2);
                a[mt][0] = __float_as_uint(xs[rb * XS_PAD + kc]);
                a[mt][1] = __float_as_uint(xs[(rb + 8) * XS_PAD + kc]);
                a[mt][2] = __float_as_uint(xs[rb * XS_PAD + kc + 4]);
                a[mt][3] = __float_as_uint(xs[(rb + 8) * XS_PAD + kc + 4]);
            }
#pragma unroll
            for (int nt = 0; nt < 6; nt++) {
                const int nb = wn * 48 + nt * 8 + (lane >> 2);
                uint32_t b0 = __float_as_uint(ws[kc * WS_PAD + nb]);
                uint32_t b1 = __float_as_uint(ws[(kc + 4) * WS_PAD + nb]);
#pragma unroll
                for (int mt = 0; mt < 4; mt++)
                    mma_tf32(c[mt][nt][0], c[mt][nt][1], c[mt][nt][2], c[mt][nt][3],
                             a[mt][0], a[mt][1], a[mt][2], a[mt][3], b0, b1);
            }
        }
        __syncthreads();
        if (kt < 63) {
            float* p = &xs[xr * XS_PAD + xk4];
            p[0] = f2tf32f(px0.x); p[1] = f2tf32f(px0.y); p[2] = f2tf32f(px0.z); p[3] = f2tf32f(px0.w);
            p = &xs[(xr + 64) * XS_PAD + xk4];
            p[0] = f2tf32f(px1.x); p[1] = f2tf32f(px1.y); p[2] = f2tf32f(px1.z); p[3] = f2tf32f(px1.w);
            p = &ws[wkr * WS_PAD + 0 + wnc];
            p[0] = f2tf32f(pw0.x); p[1] = f2tf32f(pw0.y); p[2] = f2tf32f(pw0.z); p[3] = f2tf32f(pw0.w);
            p = &ws[wkr * WS_PAD + 64 + wnc];
            p[0] = f2tf32f(pw1.x); p[1] = f2tf32f(pw1.y); p[2] = f2tf32f(pw1.z); p[3] = f2tf32f(pw1.w);
            p = &ws[wkr * WS_PAD + 128 + wnc];
            p[0] = f2tf32f(pw2.x); p[1] = f2tf32f(pw2.y); p[2] = f2tf32f(pw2.z); p[3] = f2tf32f(pw2.w);
            __syncthreads();
        }
    }

#pragma unroll
    for (int mt = 0; mt < 4; mt++) {
        const int row = row0 + wm * 64 + mt * 16 + (lane >> 2);
#pragma unroll
        for (int nt = 0; nt < 6; nt++) {
            const int gcol = wn * 48 + nt * 8 + (lane & 3) * 2;
            float* op = (gcol < 64) ? g_q : ((gcol < 128) ? g_k : g_v);
            const int lcol = gcol & 63;
            *(float2*)&op[(size_t)row * HD + lcol] = make_float2(c[mt][nt][0], c[mt][nt][1]);
            *(float2*)&op[(size_t)(row + 8) * HD + lcol] = make_float2(c[mt][nt][2], c[mt][nt][3]);
        }
    }
}

// ---------------------------------------------------------------------------
// Flash attention on tensor cores (tf32 mma), swapped roles:
// S[t][s] = (K[t].Q[s])/8, causal s<=t, softmax over s, O[t] = sum_s P V[s].
// Block: 64 t-rows, 128 threads = 4 warps; warp = 16 rows x 64 cols
// (rows warp-local -> register softmax with quad shuffles only).
// P round-trips through warp-private smem (syncwarp only) to become the
// A operand of the P.V mma. PAD=72 makes all LDS/STS patterns conflict-free.
// Causal balance: block x processes tiles x and 31-x (33 steps each).
// ---------------------------------------------------------------------------
#define APAD 72
#define ATTN_SMEM_FLOATS (4 * 64 * APAD)
#define ATTN_SMEM_BYTES  (ATTN_SMEM_FLOATS * 4)

__global__ __launch_bounds__(128) void attn_mma_kernel(float* __restrict__ out)
{
    extern __shared__ float sm[];
    float* ks = sm;                  // [t][h] tf32
    float* qs = ks + 64 * APAD;      // [s][h] tf32
    float* vs = qs + 64 * APAD;      // [s][d] tf32
    float* ps = vs + 64 * APAD;      // [t][s] tf32 probs (warp-private 16-row bands)

    const int b = blockIdx.y;
    const int tid = threadIdx.x;
    const int lane = tid & 31;
    const int warp = tid >> 5;
    const int j = lane & 3;          // quad col
    const int r = lane >> 2;         // row in group (0..7)
    const size_t bbase = (size_t)b * TLEN;
    const int wr0 = warp * 16;       // warp row base within tile

    for (int ph = 0; ph < 2; ph++) {
        const int tile = ph ? (31 - (int)blockIdx.x) : (int)blockIdx.x;
        const int t0 = tile * 64;

        __syncthreads();   // guard ks reuse across phases
        // stage K tile (tf32-rounded)
        {
            const float* gk = g_k + (bbase + t0) * HD;
#pragma unroll
            for (int i = 0; i < 8; i++) {
                const int idx = tid + i * 128;
                const int sr = idx >> 4, h4 = (idx & 15) * 4;
                float4 kv = *(const float4*)&gk[sr * HD + h4];
                *(float4*)&ks[sr * APAD + h4] =
                    make_float4(f2tf32f(kv.x), f2tf32f(kv.y), f2tf32f(kv.z), f2tf32f(kv.w));
            }
        }

        float o[8][4];
#pragma unroll
        for (int nt = 0; nt < 8; nt++)
#pragma unroll
            for (int f = 0; f < 4; f++) o[nt][f] = 0.f;
        float m0 = -1e30f, m1 = -1e30f, l0 = 0.f, l1 = 0.f;

        const int rowg0 = t0 + wr0 + r;
        const int rowg1 = rowg0 + 8;

        for (int s0 = 0; s0 <= t0; s0 += 64) {
            __syncthreads();   // prior GEMMs done with qs/vs
            {
                const float* gq = g_q + (bbase + s0) * HD;
                const float* gv = g_v + (bbase + s0) * HD;
#pragma unroll
                for (int i = 0; i < 8; i++) {
                    const int idx = tid + i * 128;
                    const int sr = idx >> 4, h4 = (idx & 15) * 4;
                    float4 qv = *(const float4*)&gq[sr * HD + h4];
                    float4 vv = *(const float4*)&gv[sr * HD + h4];
                    *(float4*)&qs[sr * APAD + h4] =
                        make_float4(f2tf32f(qv.x), f2tf32f(qv.y), f2tf32f(qv.z), f2tf32f(qv.w));
                    *(float4*)&vs[sr * APAD + h4] =
                        make_float4(f2tf32f(vv.x), f2tf32f(vv.y), f2tf32f(vv.z), f2tf32f(vv.w));
                }
            }
            __syncthreads();

            // ---- GEMM1: S = K . Q^T (m=t rows, n=s cols, k=h) ----
            float s[8][4];
#pragma unroll
            for (int nt = 0; nt < 8; nt++)
#pragma unroll
                for (int f = 0; f < 4; f++) s[nt][f] = 0.f;

#pragma unroll
            for (int kk = 0; kk < 8; kk++) {
                const int kc = kk * 8 + j;
                uint32_t a0 = __float_as_uint(ks[(wr0 + r) * APAD + kc]);
                uint32_t a1 = __float_as_uint(ks[(wr0 + r + 8) * APAD + kc]);
                uint32_t a2 = __float_as_uint(ks[(wr0 + r) * APAD + kc + 4]);
                uint32_t a3 = __float_as_uint(ks[(wr0 + r + 8) * APAD + kc + 4]);
#pragma unroll
                for (int nt = 0; nt < 8; nt++) {
                    uint32_t b0 = __float_as_uint(qs[(nt * 8 + r) * APAD + kc]);
                    uint32_t b1 = __float_as_uint(qs[(nt * 8 + r) * APAD + kc + 4]);
                    mma_tf32(s[nt][0], s[nt][1], s[nt][2], s[nt][3], a0, a1, a2, a3, b0, b1);
                }
            }

            // ---- scale + causal mask + online softmax (rows warp-local) ----
            const bool diag = (s0 == t0);
            float mx0 = -1e30f, mx1 = -1e30f;
#pragma unroll
            for (int nt = 0; nt < 8; nt++) {
                const int cg = s0 + nt * 8 + 2 * j;
                float v0 = s[nt][0] * 0.125f;
                float v1 = s[nt][1] * 0.125f;
                float v2 = s[nt][2] * 0.125f;
                float v3 = s[nt][3] * 0.125f;
                if (diag) {
                    if (cg     > rowg0) v0 = -1e30f;
                    if (cg + 1 > rowg0) v1 = -1e30f;
                    if (cg     > rowg1) v2 = -1e30f;
                    if (cg + 1 > rowg1) v3 = -1e30f;
                }
                s[nt][0] = v0; s[nt][1] = v1; s[nt][2] = v2; s[nt][3] = v3;
                mx0 = fmaxf(mx0, fmaxf(v0, v1));
                mx1 = fmaxf(mx1, fmaxf(v2, v3));
            }
            mx0 = fmaxf(mx0, __shfl_xor_sync(0xffffffffu, mx0, 1));
            mx0 = fmaxf(mx0, __shfl_xor_sync(0xffffffffu, mx0, 2));
            mx1 = fmaxf(mx1, __shfl_xor_sync(0xffffffffu, mx1, 1));
            mx1 = fmaxf(mx1, __shfl_xor_sync(0xffffffffu, mx1, 2));

            const float mn0 = fmaxf(m0, mx0);
            const float mn1 = fmaxf(m1, mx1);
            const float corr0 = __expf(m0 - mn0);
            const float corr1 = __expf(m1 - mn1);
            m0 = mn0; m1 = mn1;

            float ls0 = 0.f, ls1 = 0.f;
#pragma unroll
            for (int nt = 0; nt < 8; nt++) {
                const float p0 = f2tf32f(__expf(s[nt][0] - mn0));
                const float p1 = f2tf32f(__expf(s[nt][1] - mn0));
                const float p2 = f2tf32f(__expf(s[nt][2] - mn1));
                const float p3 = f2tf32f(__expf(s[nt][3] - mn1));
                ls0 += p0 + p1;
                ls1 += p2 + p3;
                *(float2*)&ps[(wr0 + r) * APAD + nt * 8 + 2 * j]     = make_float2(p0, p1);
                *(float2*)&ps[(wr0 + r + 8) * APAD + nt * 8 + 2 * j] = make_float2(p2, p3);
            }
            ls0 += __shfl_xor_sync(0xffffffffu, ls0, 1);
            ls0 += __shfl_xor_sync(0xffffffffu, ls0, 2);
            ls1 += __shfl_xor_sync(0xffffffffu, ls1, 1);
            ls1 += __shfl_xor_sync(0xffffffffu, ls1, 2);
            l0 = l0 * corr0 + ls0;
            l1 = l1 * corr1 + ls1;

#pragma unroll
            for (int nt = 0; nt < 8; nt++) {
                o[nt][0] *= corr0; o[nt][1] *= corr0;
                o[nt][2] *= corr1; o[nt][3] *= corr1;
            }
            __syncwarp();   // ps band visible within warp

            // ---- GEMM2: O += P . V (m=t rows, n=d cols, k=s) ----
#pragma unroll
            for (int kk = 0; kk < 8; kk++) {
                const int kc = kk * 8 + j;
                uint32_t a0 = __float_as_uint(ps[(wr0 + r) * APAD + kc]);
                uint32_t a1 = __float_as_uint(ps[(wr0 + r + 8) * APAD + kc]);
                uint32_t a2 = __float_as_uint(ps[(wr0 + r) * APAD + kc + 4]);
                uint32_t a3 = __float_as_uint(ps[(wr0 + r + 8) * APAD + kc + 4]);
#pragma unroll
                for (int nt = 0; nt < 8; nt++) {
                    uint32_t b0 = __float_as_uint(vs[kc * APAD + nt * 8 + r]);
                    uint32_t b1 = __float_as_uint(vs[(kc + 4) * APAD + nt * 8 + r]);
                    mma_tf32(o[nt][0], o[nt][1], o[nt][2], o[nt][3], a0, a1, a2, a3, b0, b1);
                }
            }
            __syncwarp();   // done reading ps before next step rewrites it
        }

        // epilogue
        const float inv0 = 1.f / l0;
        const float inv1 = 1.f / l1;
        float* op = out + (bbase + t0 + wr0) * HD;
#pragma unroll
        for (int nt = 0; nt < 8; nt++) {
            const int col = nt * 8 + 2 * j;
            *(float2*)&op[r * HD + col] =
                make_float2(o[nt][0] * inv0, o[nt][1] * inv0);
            *(float2*)&op[(r + 8) * HD + col] =
                make_float2(o[nt][2] * inv1, o[nt][3] * inv1);
        }
    }
}

extern "C" void kernel_launch(void* const* d_in, const int* in_sizes, int n_in,
                              void* d_out, int out_size)
{
    const float* x  = (const float*)d_in[0];
    const float* Wq = (const float*)d_in[1];
    const float* Wk = (const float*)d_in[2];
    const float* Wv = (const float*)d_in[3];
    float* out = (float*)d_out;

    cudaFuncSetAttribute(attn_mma_kernel, cudaFuncAttributeMaxDynamicSharedMemorySize,
                         ATTN_SMEM_BYTES);

    proj_mma_kernel<<<BT / 128, 256>>>(x, Wq, Wk, Wv);
    attn_mma_kernel<<<dim3(16, BATCH), 128, ATTN_SMEM_BYTES>>>(out);
}